// round 3
// baseline (speedup 1.0000x reference)
#include <cuda_runtime.h>
#include <cuda_bf16.h>
#include <mma.h>

using namespace nvcuda;
typedef __nv_bfloat16 bf16;

// Problem dims (fixed by the dataset)
//  B=8, C=512, H=W=64 -> N=4096, att=512
#define NB 8
#define NC 512
#define NN_ 4096
#define ND 512

// ---------------- scratch (static device globals; no allocation allowed) ----
__device__ bf16  g_h  [(size_t)NB * NC * NN_];        // GN output, [b][c][n]
__device__ bf16  g_qT [(size_t)NB * NN_ * ND];        // [b][n][d]
__device__ bf16  g_k  [(size_t)NB * ND * NN_];        // [b][d][n]
__device__ bf16  g_vT [(size_t)NB * NN_ * ND];        // [b][n][d]
__device__ float g_S  [(size_t)NB * NN_ * NN_];       // logits [b][n][m]  (512MB)
__device__ bf16  g_P  [(size_t)NB * NN_ * NN_];       // softmax [b][n][m] (256MB)
__device__ bf16  g_hf [(size_t)NB * ND * NN_];        // attn out [b][d][n]
__device__ bf16  g_wq [ND * NC];
__device__ bf16  g_wk [ND * NC];
__device__ bf16  g_wv [ND * NC];
__device__ bf16  g_wp [NC * ND];

// ---------------- weight fp32 -> bf16 --------------------------------------
__global__ void cvt_w_kernel(const float* __restrict__ qw, const float* __restrict__ kw,
                             const float* __restrict__ vw, const float* __restrict__ pw) {
    int i = blockIdx.x * 256 + threadIdx.x;
    if (i < ND * NC) {
        g_wq[i] = __float2bfloat16(qw[i]);
        g_wk[i] = __float2bfloat16(kw[i]);
        g_wv[i] = __float2bfloat16(vw[i]);
        g_wp[i] = __float2bfloat16(pw[i]);
    }
}

// ---------------- GroupNorm (32 groups of 16 channels) ----------------------
// one block per (b, g): 16*4096 = 65536 elems
__global__ __launch_bounds__(256) void gn_kernel(
    const float* __restrict__ x, const float* __restrict__ gamma,
    const float* __restrict__ beta)
{
    int bg = blockIdx.x;
    int b = bg >> 5, g = bg & 31;
    const float4* xp = (const float4*)(x + ((size_t)(b * NC + g * 16)) * NN_);
    int t = threadIdx.x;

    float s = 0.f, ss = 0.f;
    for (int i = t; i < 16384; i += 256) {
        float4 v = xp[i];
        s  += v.x + v.y + v.z + v.w;
        ss += v.x * v.x + v.y * v.y + v.z * v.z + v.w * v.w;
    }
    __shared__ float rs[256], rq[256];
    rs[t] = s; rq[t] = ss;
    __syncthreads();
    for (int st = 128; st > 0; st >>= 1) {
        if (t < st) { rs[t] += rs[t + st]; rq[t] += rq[t + st]; }
        __syncthreads();
    }
    float mean = rs[0] * (1.f / 65536.f);
    float var  = rq[0] * (1.f / 65536.f) - mean * mean;
    float inv  = rsqrtf(var + 1e-5f);

    bf16* hp = g_h + ((size_t)(b * NC + g * 16)) * NN_;
    for (int i = t; i < 16384; i += 256) {
        int c = g * 16 + (i >> 10);             // 1024 float4 per channel row
        float ga = gamma[c] * inv;
        float be = beta[c] - mean * ga;
        float4 v = xp[i];
        __nv_bfloat162 p0 = __floats2bfloat162_rn(v.x * ga + be, v.y * ga + be);
        __nv_bfloat162 p1 = __floats2bfloat162_rn(v.z * ga + be, v.w * ga + be);
        ((__nv_bfloat162*)hp)[2 * i]     = p0;
        ((__nv_bfloat162*)hp)[2 * i + 1] = p1;
    }
}

// ---------------- generic bf16 wmma GEMM ------------------------------------
// C[M,N] = alpha * A[M,K] @ B[K,N] (+ bias[Mrow]) (+ residual) ; NN row-major.
// OMODE: 0 = fp32 normal store (+optional residual), 1 = bf16 normal, 2 = bf16
// transposed store (C[col*ldC + row]).
#define BM 128
#define BN 128
#define BK 32
#define LDAS 40
#define LDBS 136

template<int OMODE>
__global__ __launch_bounds__(256)
void gemm_kernel(const bf16* __restrict__ A, const bf16* __restrict__ Bm,
                 void* __restrict__ Cv,
                 const float* __restrict__ bias, const float* __restrict__ resid,
                 int M, int N, int K, int ldA, int ldB, int ldC,
                 long long sA, long long sB, long long sC, long long sR,
                 float alpha)
{
    __shared__ __align__(16) bf16 As[2][BM * LDAS];
    __shared__ __align__(16) bf16 Bs[2][BK * LDBS];
    __shared__ float stag[8][256];

    int bz = blockIdx.z;
    A  += sA * bz;
    Bm += sB * bz;
    int bm = blockIdx.y * BM;
    int bn = blockIdx.x * BN;
    int t = threadIdx.x;
    int w = t >> 5, lane = t & 31;
    int wm = w >> 2, wn = w & 3;    // 2 x 4 warp grid -> warp tile 64 x 32

    wmma::fragment<wmma::matrix_a, 16, 16, 16, bf16, wmma::row_major> fa[4];
    wmma::fragment<wmma::matrix_b, 16, 16, 16, bf16, wmma::row_major> fb[2];
    wmma::fragment<wmma::accumulator, 16, 16, 16, float> fc[4][2];
#pragma unroll
    for (int i = 0; i < 4; i++)
#pragma unroll
        for (int j = 0; j < 2; j++) wmma::fill_fragment(fc[i][j], 0.f);

    // preload tile 0
#pragma unroll
    for (int u = 0; u < 2; u++) {
        int idx = t + u * 256;
        int r = idx >> 2, c = (idx & 3) * 8;
        *(uint4*)&As[0][r * LDAS + c] =
            *(const uint4*)&A[(size_t)(bm + r) * ldA + c];
    }
#pragma unroll
    for (int u = 0; u < 2; u++) {
        int idx = t + u * 256;
        int r = idx >> 4, c = (idx & 15) * 8;
        *(uint4*)&Bs[0][r * LDBS + c] =
            *(const uint4*)&Bm[(size_t)r * ldB + bn + c];
    }
    __syncthreads();

    int nk = K / BK;
    for (int kt = 0; kt < nk; kt++) {
        uint4 ra[2], rb[2];
        bool pf = (kt + 1 < nk);
        int k0n = (kt + 1) * BK;
        if (pf) {
#pragma unroll
            for (int u = 0; u < 2; u++) {
                int idx = t + u * 256;
                ra[u] = *(const uint4*)&A[(size_t)(bm + (idx >> 2)) * ldA + k0n + (idx & 3) * 8];
            }
#pragma unroll
            for (int u = 0; u < 2; u++) {
                int idx = t + u * 256;
                rb[u] = *(const uint4*)&Bm[(size_t)(k0n + (idx >> 4)) * ldB + bn + (idx & 15) * 8];
            }
        }
        int buf = kt & 1;
#pragma unroll
        for (int ks = 0; ks < 2; ks++) {
#pragma unroll
            for (int i = 0; i < 4; i++)
                wmma::load_matrix_sync(fa[i], &As[buf][(wm * 64 + i * 16) * LDAS + ks * 16], LDAS);
#pragma unroll
            for (int j = 0; j < 2; j++)
                wmma::load_matrix_sync(fb[j], &Bs[buf][(ks * 16) * LDBS + wn * 32 + j * 16], LDBS);
#pragma unroll
            for (int i = 0; i < 4; i++)
#pragma unroll
                for (int j = 0; j < 2; j++)
                    wmma::mma_sync(fc[i][j], fa[i], fb[j], fc[i][j]);
        }
        if (pf) {
            int nb = buf ^ 1;
#pragma unroll
            for (int u = 0; u < 2; u++) {
                int idx = t + u * 256;
                *(uint4*)&As[nb][(idx >> 2) * LDAS + (idx & 3) * 8] = ra[u];
            }
#pragma unroll
            for (int u = 0; u < 2; u++) {
                int idx = t + u * 256;
                *(uint4*)&Bs[nb][(idx >> 4) * LDBS + (idx & 15) * 8] = rb[u];
            }
        }
        __syncthreads();
    }

    // epilogue: per-warp staging through shared, vectorized 16B stores
#pragma unroll
    for (int i = 0; i < 4; i++) {
#pragma unroll
        for (int j = 0; j < 2; j++) {
            wmma::store_matrix_sync(stag[w], fc[i][j], 16, wmma::mem_row_major);
            __syncwarp();
            int row0 = bm + wm * 64 + i * 16;
            int col0 = bn + wn * 32 + j * 16;
            if (OMODE == 2) {
                // transposed store: thread owns 8 consecutive rows @ fixed col
                int c = lane >> 1, r0 = (lane & 1) * 8;
                __align__(16) bf16 vals[8];
#pragma unroll
                for (int u = 0; u < 8; u++) {
                    float v = stag[w][(r0 + u) * 16 + c] * alpha;
                    if (bias) v += bias[row0 + r0 + u];
                    vals[u] = __float2bfloat16(v);
                }
                bf16* C = (bf16*)Cv + sC * bz;
                *(uint4*)&C[(size_t)(col0 + c) * ldC + row0 + r0] = *(uint4*)vals;
            } else {
                int r = lane >> 1, c0 = (lane & 1) * 8;
                float v[8];
#pragma unroll
                for (int u = 0; u < 8; u++) v[u] = stag[w][r * 16 + c0 + u] * alpha;
                if (bias) {
                    float bv = bias[row0 + r];
#pragma unroll
                    for (int u = 0; u < 8; u++) v[u] += bv;
                }
                if (OMODE == 0) {
                    float* C = (float*)Cv + sC * bz;
                    size_t off = (size_t)(row0 + r) * ldC + col0 + c0;
                    if (resid) {
                        const float* R = resid + sR * bz;
#pragma unroll
                        for (int u = 0; u < 8; u++) v[u] += R[off + u];
                    }
                    *(float4*)&C[off]     = make_float4(v[0], v[1], v[2], v[3]);
                    *(float4*)&C[off + 4] = make_float4(v[4], v[5], v[6], v[7]);
                } else {
                    __align__(16) bf16 o[8];
#pragma unroll
                    for (int u = 0; u < 8; u++) o[u] = __float2bfloat16(v[u]);
                    bf16* C = (bf16*)Cv + sC * bz;
                    *(uint4*)&C[(size_t)(row0 + r) * ldC + col0 + c0] = *(uint4*)o;
                }
            }
            __syncwarp();
        }
    }
}

// ---------------- softmax over rows of S (4096 wide), write bf16 P ----------
__global__ __launch_bounds__(256) void softmax_kernel() {
    size_t row = blockIdx.x;                        // 8*4096 rows
    const float4* sp = (const float4*)(g_S + row * NN_);
    bf16* pp = g_P + row * NN_;
    int t = threadIdx.x;

    float4 v[4];
    float mx = -1e30f;
#pragma unroll
    for (int u = 0; u < 4; u++) {
        v[u] = sp[t + u * 256];
        mx = fmaxf(mx, fmaxf(fmaxf(v[u].x, v[u].y), fmaxf(v[u].z, v[u].w)));
    }
    __shared__ float red[256];
    red[t] = mx; __syncthreads();
    for (int st = 128; st > 0; st >>= 1) {
        if (t < st) red[t] = fmaxf(red[t], red[t + st]);
        __syncthreads();
    }
    float m = red[0];
    __syncthreads();

    float e[16];
    float sum = 0.f;
#pragma unroll
    for (int u = 0; u < 4; u++) {
        e[4 * u + 0] = __expf(v[u].x - m);
        e[4 * u + 1] = __expf(v[u].y - m);
        e[4 * u + 2] = __expf(v[u].z - m);
        e[4 * u + 3] = __expf(v[u].w - m);
        sum += e[4 * u + 0] + e[4 * u + 1] + e[4 * u + 2] + e[4 * u + 3];
    }
    red[t] = sum; __syncthreads();
    for (int st = 128; st > 0; st >>= 1) {
        if (t < st) red[t] += red[t + st];
        __syncthreads();
    }
    float inv = 1.f / red[0];
#pragma unroll
    for (int u = 0; u < 4; u++) {
        int i = t + u * 256;
        __nv_bfloat162 p0 = __floats2bfloat162_rn(e[4 * u + 0] * inv, e[4 * u + 1] * inv);
        __nv_bfloat162 p1 = __floats2bfloat162_rn(e[4 * u + 2] * inv, e[4 * u + 3] * inv);
        ((__nv_bfloat162*)pp)[2 * i]     = p0;
        ((__nv_bfloat162*)pp)[2 * i + 1] = p1;
    }
}

// ---------------- launch -----------------------------------------------------
static void* sym_addr(const void* s) { void* p = nullptr; cudaGetSymbolAddress(&p, s); return p; }

extern "C" void kernel_launch(void* const* d_in, const int* in_sizes, int n_in,
                              void* d_out, int out_size) {
    const float* x   = (const float*)d_in[0];
    const float* gnw = (const float*)d_in[1];
    const float* gnb = (const float*)d_in[2];
    const float* qw  = (const float*)d_in[3];
    const float* qb  = (const float*)d_in[4];
    const float* kw  = (const float*)d_in[5];
    const float* kb  = (const float*)d_in[6];
    const float* vw  = (const float*)d_in[7];
    const float* vb  = (const float*)d_in[8];
    const float* pw  = (const float*)d_in[9];
    const float* pb  = (const float*)d_in[10];

    bf16*  p_h  = (bf16*) sym_addr(g_h);
    bf16*  p_qT = (bf16*) sym_addr(g_qT);
    bf16*  p_k  = (bf16*) sym_addr(g_k);
    bf16*  p_vT = (bf16*) sym_addr(g_vT);
    float* p_S  = (float*)sym_addr(g_S);
    bf16*  p_P  = (bf16*) sym_addr(g_P);
    bf16*  p_hf = (bf16*) sym_addr(g_hf);
    bf16*  p_wq = (bf16*) sym_addr(g_wq);
    bf16*  p_wk = (bf16*) sym_addr(g_wk);
    bf16*  p_wv = (bf16*) sym_addr(g_wv);
    bf16*  p_wp = (bf16*) sym_addr(g_wp);

    const long long sHW = (long long)NC * NN_;        // 2097152
    const long long sSS = (long long)NN_ * NN_;       // 16777216
    const float scale = 0.044194173824159216f;        // 512^-0.5

    cvt_w_kernel<<<1024, 256>>>(qw, kw, vw, pw);
    gn_kernel<<<NB * 32, 256>>>(x, gnw, gnb);

    // K = Wk @ h              -> g_k [b][d][n]
    gemm_kernel<1><<<dim3(32, 4, NB), 256>>>(p_wk, p_h, p_k, kb, nullptr,
        ND, NN_, NC, NC, NN_, NN_, 0, sHW, sHW, 0, 1.f);
    // Qt = (Wq @ h)^T         -> g_qT [b][n][d]
    gemm_kernel<2><<<dim3(32, 4, NB), 256>>>(p_wq, p_h, p_qT, qb, nullptr,
        ND, NN_, NC, NC, NN_, ND, 0, sHW, sHW, 0, 1.f);
    // Vt = (Wv @ h)^T         -> g_vT [b][n][d]
    gemm_kernel<2><<<dim3(32, 4, NB), 256>>>(p_wv, p_h, p_vT, vb, nullptr,
        ND, NN_, NC, NC, NN_, ND, 0, sHW, sHW, 0, 1.f);
    // S = scale * Qt @ K      -> g_S [b][n][m] fp32
    gemm_kernel<0><<<dim3(32, 32, NB), 256>>>(p_qT, p_k, p_S, nullptr, nullptr,
        NN_, NN_, ND, ND, NN_, NN_, (long long)NN_ * ND, sHW, sSS, 0, scale);
    // P = softmax(S)
    softmax_kernel<<<NB * NN_, 256>>>();
    // hf = (P @ Vt)^T         -> g_hf [b][d][n]
    gemm_kernel<2><<<dim3(4, 32, NB), 256>>>(p_P, p_vT, p_hf, nullptr, nullptr,
        NN_, ND, NN_, NN_, ND, NN_, sSS, (long long)NN_ * ND, sHW, 0, 1.f);
    // out = x + Wp @ hf + pb  -> d_out fp32
    gemm_kernel<0><<<dim3(32, 4, NB), 256>>>(p_wp, p_hf, d_out, pb, x,
        NC, NN_, ND, ND, NN_, NN_, 0, sHW, sHW, sHW, 1.f);
}

// round 7
// speedup vs baseline: 1.8918x; 1.8918x over previous
#include <cuda_runtime.h>
#include <cuda_bf16.h>
#include <mma.h>
#include <cstdint>

using namespace nvcuda;
typedef __nv_bfloat16 bf16;

// Problem dims: B=8, C=512, H=W=64 -> N=4096, att=512
#define NB 8
#define NC 512
#define NN_ 4096
#define ND 512

// ---------------- scratch (static device globals) ---------------------------
__device__ __align__(1024) bf16  g_hT [(size_t)NB * NN_ * NC];  // [b][n][c]
__device__ __align__(1024) bf16  g_qT [(size_t)NB * NN_ * ND];  // [b][n][d]
__device__ __align__(1024) bf16  g_kT [(size_t)NB * NN_ * ND];  // [b][m][d]
__device__ __align__(1024) bf16  g_v  [(size_t)NB * ND * NN_];  // [b][d][m]
__device__ __align__(1024) bf16  g_S  [(size_t)NB * NN_ * NN_]; // [b][n][m] (256MB)
__device__ __align__(1024) bf16  g_hfT[(size_t)NB * NN_ * ND];  // [b][n][d]
__device__ __align__(1024) bf16  g_wq [ND * NC];
__device__ __align__(1024) bf16  g_wk [ND * NC];
__device__ __align__(1024) bf16  g_wv [ND * NC];
__device__ __align__(1024) bf16  g_wp [NC * ND];
__device__ float2 g_stats[NB * 32];                             // per (b,g): mean, inv

// ---------------- async-copy helpers -----------------------------------------
__device__ __forceinline__ uint32_t smem_u32(const void* p) {
    uint32_t a;
    asm("{ .reg .u64 t; cvta.to.shared.u64 t, %1; cvt.u32.u64 %0, t; }" : "=r"(a) : "l"(p));
    return a;
}
__device__ __forceinline__ void cp_async16(uint32_t s, const void* g) {
    asm volatile("cp.async.cg.shared.global [%0], [%1], 16;" :: "r"(s), "l"(g));
}
#define CP_COMMIT()  asm volatile("cp.async.commit_group;" ::: "memory")
#define CP_WAIT2()   asm volatile("cp.async.wait_group 2;" ::: "memory")

// ---------------- HMMA GEMM: D[M,N] = alpha * A[M,K] @ B[N,K]^T --------------
// A, B bf16, K-contiguous (ldA=ldB=K), D row-major ld=N.
// OM: 0 = bf16 out + col bias[n]; 1 = bf16 out + row bias[m];
//     2 = bf16 out * alpha;       4 = fp32 out + row bias[m] + residual.
#define BM 128
#define BN 128
#define BK 64
#define LDS_ 72                   // padded leading dim (halves)
#define STAGES 4
#define STAGE_BYTES 32768          // (A 128x64 + B 128x64) * 2B w/ pad: 2*128*72*2 = 36864? no:
// NOTE: rows are stored padded: 128 rows * 72 halves * 2B = 18432 B per matrix.
#undef STAGE_BYTES
#define A_BYTES (BM * LDS_ * 2)    // 18432
#define STAGE_BYTES (2 * A_BYTES)  // 36864
#define STAG_BYTES (8 * 256 * 4)   // epilogue staging, 8KB
#define GEMM_SMEM (STAGES * STAGE_BYTES + STAG_BYTES)

template<int OM>
__global__ __launch_bounds__(256, 1)
void hm_gemm(const bf16* __restrict__ A, const bf16* __restrict__ B, void* __restrict__ Cv,
             const float* __restrict__ bias, const float* __restrict__ resid,
             int M, int N, int K,
             long long sA, long long sB, long long sC, long long sR, float alpha)
{
    extern __shared__ __align__(16) char smem[];
    float* stag = (float*)(smem + STAGES * STAGE_BYTES);

    int t = threadIdx.x, w = t >> 5, lane = t & 31;
    int wm = w >> 2, wn = w & 3;                 // 2 x 4 warps -> warp tile 64 x 32
    int bz = blockIdx.z;
    const bf16* Ab = A + sA * bz;
    const bf16* Bb = B + sB * bz;
    int bm = blockIdx.y * BM;
    int bn = blockIdx.x * BN;

    uint32_t sbase = smem_u32(smem);

    // per-stage chunk load: A then B, 128 rows x 8 chunks(16B) each = 4 cp/thread/matrix
    auto load_chunk = [&](int kc, int s) {
        uint32_t sa = sbase + s * STAGE_BYTES;
        uint32_t sb = sa + A_BYTES;
        int k0 = kc * BK;
#pragma unroll
        for (int u = 0; u < 4; u++) {
            int idx = t + u * 256;
            int r = idx >> 3, c = idx & 7;
            cp_async16(sa + r * (LDS_ * 2) + c * 16,
                       Ab + (size_t)(bm + r) * K + k0 + c * 8);
        }
#pragma unroll
        for (int u = 0; u < 4; u++) {
            int idx = t + u * 256;
            int r = idx >> 3, c = idx & 7;
            cp_async16(sb + r * (LDS_ * 2) + c * 16,
                       Bb + (size_t)(bn + r) * K + k0 + c * 8);
        }
        CP_COMMIT();
    };

    wmma::fragment<wmma::matrix_a, 16, 16, 16, bf16, wmma::row_major> fa[4];
    wmma::fragment<wmma::matrix_b, 16, 16, 16, bf16, wmma::col_major> fb[2];
    wmma::fragment<wmma::accumulator, 16, 16, 16, float> fc[4][2];
#pragma unroll
    for (int i = 0; i < 4; i++)
#pragma unroll
        for (int j = 0; j < 2; j++) wmma::fill_fragment(fc[i][j], 0.f);

    int nK = K / BK;
    // prologue: stages 0..2
    load_chunk(0, 0);
    load_chunk(1, 1);
    load_chunk(2, 2);

    for (int kc = 0; kc < nK; kc++) {
        int s = kc & (STAGES - 1);
        CP_WAIT2();
        __syncthreads();
        // prefetch stage kc+3 (or empty commit to keep group accounting sound)
        if (kc + 3 < nK) load_chunk(kc + 3, (kc + 3) & (STAGES - 1));
        else CP_COMMIT();

        const bf16* As = (const bf16*)(smem + s * STAGE_BYTES);
        const bf16* Bs = As + BM * LDS_;
#pragma unroll
        for (int ks = 0; ks < 4; ks++) {
#pragma unroll
            for (int i = 0; i < 4; i++)
                wmma::load_matrix_sync(fa[i], As + (wm * 64 + i * 16) * LDS_ + ks * 16, LDS_);
#pragma unroll
            for (int j = 0; j < 2; j++)
                wmma::load_matrix_sync(fb[j], Bs + (wn * 32 + j * 16) * LDS_ + ks * 16, LDS_);
#pragma unroll
            for (int i = 0; i < 4; i++)
#pragma unroll
                for (int j = 0; j < 2; j++)
                    wmma::mma_sync(fc[i][j], fa[i], fb[j], fc[i][j]);
        }
        __syncthreads();
    }

    // ---------------- epilogue: warp-staged, vectorized ----------------------
    float* st = stag + w * 256;
#pragma unroll
    for (int i = 0; i < 4; i++) {
#pragma unroll
        for (int j = 0; j < 2; j++) {
            wmma::store_matrix_sync(st, fc[i][j], 16, wmma::mem_row_major);
            __syncwarp();
            int row0 = bm + wm * 64 + i * 16;
            int col0 = bn + wn * 32 + j * 16;
            int r = lane >> 1, c0 = (lane & 1) * 8;
            int row = row0 + r;
            float vv[8];
#pragma unroll
            for (int u = 0; u < 8; u++) vv[u] = st[r * 16 + c0 + u];
            if (OM == 2) {
#pragma unroll
                for (int u = 0; u < 8; u++) vv[u] *= alpha;
            }
            if (OM == 0) {
#pragma unroll
                for (int u = 0; u < 8; u++) vv[u] += bias[col0 + c0 + u];
            }
            if (OM == 1 || OM == 4) {
                float bv = bias[row];
#pragma unroll
                for (int u = 0; u < 8; u++) vv[u] += bv;
            }
            size_t off = (size_t)row * N + col0 + c0;
            if (OM == 4) {
                float* C = (float*)Cv + sC * bz;
                const float* R = resid + sR * bz;
#pragma unroll
                for (int u = 0; u < 8; u++) vv[u] += R[off + u];
                *(float4*)&C[off]     = make_float4(vv[0], vv[1], vv[2], vv[3]);
                *(float4*)&C[off + 4] = make_float4(vv[4], vv[5], vv[6], vv[7]);
            } else {
                bf16* C = (bf16*)Cv + sC * bz;
                __align__(16) bf16 o[8];
#pragma unroll
                for (int u = 0; u < 8; u += 2)
                    *(__nv_bfloat162*)&o[u] = __floats2bfloat162_rn(vv[u], vv[u + 1]);
                *(uint4*)&C[off] = *(uint4*)o;
            }
            __syncwarp();
        }
    }
}

// ---------------- weight fp32 -> bf16 ----------------------------------------
__global__ void cvt_w_kernel(const float* __restrict__ qw, const float* __restrict__ kw,
                             const float* __restrict__ vw, const float* __restrict__ pw) {
    int i = blockIdx.x * 256 + threadIdx.x;
    if (i < ND * NC) {
        g_wq[i] = __float2bfloat16(qw[i]);
        g_wk[i] = __float2bfloat16(kw[i]);
        g_wv[i] = __float2bfloat16(vw[i]);
        g_wp[i] = __float2bfloat16(pw[i]);
    }
}

// ---------------- GN phase 1: per-(b,g) stats ---------------------------------
__global__ __launch_bounds__(256) void gn_stats_kernel(const float* __restrict__ x) {
    int bg = blockIdx.x;
    int b = bg >> 5, g = bg & 31;
    const float4* xp = (const float4*)(x + ((size_t)(b * NC + g * 16)) * NN_);
    int t = threadIdx.x;
    float s = 0.f, ss = 0.f;
    for (int i = t; i < 16384; i += 256) {
        float4 v = xp[i];
        s  += v.x + v.y + v.z + v.w;
        ss += v.x * v.x + v.y * v.y + v.z * v.z + v.w * v.w;
    }
    __shared__ float rs[256], rq[256];
    rs[t] = s; rq[t] = ss;
    __syncthreads();
    for (int st = 128; st > 0; st >>= 1) {
        if (t < st) { rs[t] += rs[t + st]; rq[t] += rq[t + st]; }
        __syncthreads();
    }
    if (t == 0) {
        float mean = rs[0] * (1.f / 65536.f);
        float var  = rq[0] * (1.f / 65536.f) - mean * mean;
        g_stats[bg] = make_float2(mean, rsqrtf(var + 1e-5f));
    }
}

// ---------------- GN phase 2: normalize + transpose -> hT [b][n][c] -----------
__global__ __launch_bounds__(256) void gn_apply_kernel(
    const float* __restrict__ x, const float* __restrict__ gamma,
    const float* __restrict__ beta)
{
    __shared__ __align__(16) bf16 ts[128][72];
    int n0 = blockIdx.x * 128, c0 = blockIdx.y * 64, b = blockIdx.z;
    int t = threadIdx.x;
#pragma unroll
    for (int u = 0; u < 8; u++) {
        int idx = t + u * 256;               // 2048 = 64c x 32 (n in float4)
        int c = idx >> 5, nv = idx & 31;
        float2 st = g_stats[b * 32 + ((c0 + c) >> 4)];
        float sc = gamma[c0 + c] * st.y;
        float sh = beta[c0 + c] - st.x * sc;
        float4 v = *(const float4*)(x + ((size_t)(b * NC + c0 + c)) * NN_ + n0 + nv * 4);
        ts[nv * 4 + 0][c] = __float2bfloat16(v.x * sc + sh);
        ts[nv * 4 + 1][c] = __float2bfloat16(v.y * sc + sh);
        ts[nv * 4 + 2][c] = __float2bfloat16(v.z * sc + sh);
        ts[nv * 4 + 3][c] = __float2bfloat16(v.w * sc + sh);
    }
    __syncthreads();
#pragma unroll
    for (int u = 0; u < 4; u++) {
        int idx = t + u * 256;               // 1024 = 128n x 8 (c in uint4)
        int n = idx >> 3, cq = idx & 7;
        uint4 val = *(uint4*)&ts[n][cq * 8];
        *(uint4*)&g_hT[((size_t)(b * NN_ + n0 + n)) * NC + c0 + cq * 8] = val;
    }
}

// ---------------- softmax in place over bf16 S rows ---------------------------
__global__ __launch_bounds__(256) void softmax_kernel() {
    size_t row = blockIdx.x;
    uint4* sp = (uint4*)(g_S + row * NN_);   // 512 uint4 per row
    int t = threadIdx.x;
    uint4 v0 = sp[t], v1 = sp[t + 256];
    float e[16];
    {
        const uint32_t* w0 = (const uint32_t*)&v0;
        const uint32_t* w1 = (const uint32_t*)&v1;
#pragma unroll
        for (int i = 0; i < 4; i++) {
            float2 a = __bfloat1622float2(*(__nv_bfloat162*)&w0[i]);
            e[2 * i] = a.x; e[2 * i + 1] = a.y;
            float2 c = __bfloat1622float2(*(__nv_bfloat162*)&w1[i]);
            e[8 + 2 * i] = c.x; e[8 + 2 * i + 1] = c.y;
        }
    }
    float mx = -1e30f;
#pragma unroll
    for (int i = 0; i < 16; i++) mx = fmaxf(mx, e[i]);
    __shared__ float red[256];
    red[t] = mx; __syncthreads();
    for (int st = 128; st > 0; st >>= 1) {
        if (t < st) red[t] = fmaxf(red[t], red[t + st]);
        __syncthreads();
    }
    float m = red[0];
    __syncthreads();
    float sum = 0.f;
#pragma unroll
    for (int i = 0; i < 16; i++) { e[i] = __expf(e[i] - m); sum += e[i]; }
    red[t] = sum; __syncthreads();
    for (int st = 128; st > 0; st >>= 1) {
        if (t < st) red[t] += red[t + st];
        __syncthreads();
    }
    float inv = 1.f / red[0];
    uint4 o0, o1;
    uint32_t* w0 = (uint32_t*)&o0;
    uint32_t* w1 = (uint32_t*)&o1;
#pragma unroll
    for (int i = 0; i < 4; i++) {
        __nv_bfloat162 a = __floats2bfloat162_rn(e[2 * i] * inv, e[2 * i + 1] * inv);
        w0[i] = *(uint32_t*)&a;
        __nv_bfloat162 c = __floats2bfloat162_rn(e[8 + 2 * i] * inv, e[9 + 2 * i] * inv);
        w1[i] = *(uint32_t*)&c;
    }
    sp[t] = o0; sp[t + 256] = o1;
}

// ---------------- launch ------------------------------------------------------
static void* sym_addr(const void* s) { void* p = nullptr; cudaGetSymbolAddress(&p, s); return p; }

extern "C" void kernel_launch(void* const* d_in, const int* in_sizes, int n_in,
                              void* d_out, int out_size) {
    const float* x   = (const float*)d_in[0];
    const float* gnw = (const float*)d_in[1];
    const float* gnb = (const float*)d_in[2];
    const float* qw  = (const float*)d_in[3];
    const float* qb  = (const float*)d_in[4];
    const float* kw  = (const float*)d_in[5];
    const float* kb  = (const float*)d_in[6];
    const float* vw  = (const float*)d_in[7];
    const float* vb  = (const float*)d_in[8];
    const float* pw  = (const float*)d_in[9];
    const float* pb  = (const float*)d_in[10];

    bf16* p_hT  = (bf16*)sym_addr(g_hT);
    bf16* p_qT  = (bf16*)sym_addr(g_qT);
    bf16* p_kT  = (bf16*)sym_addr(g_kT);
    bf16* p_v   = (bf16*)sym_addr(g_v);
    bf16* p_S   = (bf16*)sym_addr(g_S);
    bf16* p_hfT = (bf16*)sym_addr(g_hfT);
    bf16* p_wq  = (bf16*)sym_addr(g_wq);
    bf16* p_wk  = (bf16*)sym_addr(g_wk);
    bf16* p_wv  = (bf16*)sym_addr(g_wv);
    bf16* p_wp  = (bf16*)sym_addr(g_wp);

    static bool attr_done = false;
    if (!attr_done) {
        cudaFuncSetAttribute(hm_gemm<0>, cudaFuncAttributeMaxDynamicSharedMemorySize, GEMM_SMEM);
        cudaFuncSetAttribute(hm_gemm<1>, cudaFuncAttributeMaxDynamicSharedMemorySize, GEMM_SMEM);
        cudaFuncSetAttribute(hm_gemm<2>, cudaFuncAttributeMaxDynamicSharedMemorySize, GEMM_SMEM);
        cudaFuncSetAttribute(hm_gemm<4>, cudaFuncAttributeMaxDynamicSharedMemorySize, GEMM_SMEM);
        attr_done = true;
    }

    const long long sT  = (long long)NN_ * ND;   // batch stride for hT/qT/kT/v/hfT
    const long long sSS = (long long)NN_ * NN_;
    const float scale = 0.044194173824159216f;   // 512^-0.5

    cvt_w_kernel<<<1024, 256>>>(qw, kw, vw, pw);
    gn_stats_kernel<<<NB * 32, 256>>>(x);
    gn_apply_kernel<<<dim3(32, 8, NB), 256>>>(x, gnw, gnb);

    // qT[n,d] = hT @ Wq^T + qb[d]   (col bias)
    hm_gemm<0><<<dim3(4, 32, NB), 256, GEMM_SMEM>>>(p_hT, p_wq, p_qT, qb, nullptr,
        NN_, ND, NC, sT, 0, sT, 0, 1.f);
    // kT[m,d] = hT @ Wk^T + kb[d]
    hm_gemm<0><<<dim3(4, 32, NB), 256, GEMM_SMEM>>>(p_hT, p_wk, p_kT, kb, nullptr,
        NN_, ND, NC, sT, 0, sT, 0, 1.f);
    // v[d,m] = Wv @ hT^T + vb[d]    (row bias)
    hm_gemm<1><<<dim3(32, 4, NB), 256, GEMM_SMEM>>>(p_wv, p_hT, p_v, vb, nullptr,
        ND, NN_, NC, 0, sT, sT, 0, 1.f);
    // S[n,m] = scale * qT @ kT^T    (bf16)
    hm_gemm<2><<<dim3(32, 32, NB), 256, GEMM_SMEM>>>(p_qT, p_kT, p_S, nullptr, nullptr,
        NN_, NN_, ND, sT, sT, sSS, 0, scale);
    // P = softmax(S) in place
    softmax_kernel<<<NB * NN_, 256>>>();
    // hfT[n,d] = P @ v^T
    hm_gemm<2><<<dim3(4, 32, NB), 256, GEMM_SMEM>>>(p_S, p_v, p_hfT, nullptr, nullptr,
        NN_, ND, NN_, sSS, sT, sT, 0, 1.f);
    // out[c,n] = Wp @ hfT^T + pb[c] + x   (fp32 + residual)
    hm_gemm<4><<<dim3(32, 4, NB), 256, GEMM_SMEM>>>(p_wp, p_hfT, d_out, pb, x,
        NC, NN_, ND, 0, sT, (long long)NC * NN_, (long long)NC * NN_, 1.f);
}

// round 8
// speedup vs baseline: 2.5359x; 1.3405x over previous
#include <cuda_runtime.h>
#include <cuda_bf16.h>
#include <cstdint>

typedef __nv_bfloat16 bf16;

// Problem dims: B=8, C=512, H=W=64 -> N=4096, att=512
#define NB 8
#define NC 512
#define NN_ 4096
#define ND 512

// ---------------- scratch (static device globals) ---------------------------
__device__ __align__(1024) bf16  g_hT [(size_t)NB * NN_ * NC];  // [b][n][c]
__device__ __align__(1024) bf16  g_qT [(size_t)NB * NN_ * ND];  // [b][n][d]
__device__ __align__(1024) bf16  g_kT [(size_t)NB * NN_ * ND];  // [b][m][d]
__device__ __align__(1024) bf16  g_v  [(size_t)NB * ND * NN_];  // [b][d][m]
__device__ __align__(1024) bf16  g_S  [(size_t)NB * NN_ * NN_]; // [b][n][m] (256MB)
__device__ __align__(1024) bf16  g_hfT[(size_t)NB * NN_ * ND];  // [b][n][d]
__device__ __align__(1024) bf16  g_wq [ND * NC];
__device__ __align__(1024) bf16  g_wk [ND * NC];
__device__ __align__(1024) bf16  g_wv [ND * NC];
__device__ __align__(1024) bf16  g_wp [NC * ND];
__device__ float2 g_stats[NB * 32];                             // per (b,g): mean, inv

// ---------------- helpers -----------------------------------------------------
__device__ __forceinline__ uint32_t smem_u32(const void* p) {
    uint32_t a;
    asm("{ .reg .u64 t; cvta.to.shared.u64 t, %1; cvt.u32.u64 %0, t; }" : "=r"(a) : "l"(p));
    return a;
}
__device__ __forceinline__ void cp_async16(uint32_t s, const void* g) {
    asm volatile("cp.async.cg.shared.global [%0], [%1], 16;" :: "r"(s), "l"(g));
}
#define CP_COMMIT()  asm volatile("cp.async.commit_group;" ::: "memory")
#define CP_WAIT2()   asm volatile("cp.async.wait_group 2;" ::: "memory")

__device__ __forceinline__ void ldm4(uint32_t* r, uint32_t addr) {
    asm volatile("ldmatrix.sync.aligned.m8n8.x4.shared.b16 {%0,%1,%2,%3}, [%4];"
        : "=r"(r[0]), "=r"(r[1]), "=r"(r[2]), "=r"(r[3]) : "r"(addr));
}
__device__ __forceinline__ void mma16816(float* d, const uint32_t* a, const uint32_t* b) {
    asm volatile(
        "mma.sync.aligned.m16n8k16.row.col.f32.bf16.bf16.f32 "
        "{%0,%1,%2,%3}, {%4,%5,%6,%7}, {%8,%9}, {%0,%1,%2,%3};"
        : "+f"(d[0]), "+f"(d[1]), "+f"(d[2]), "+f"(d[3])
        : "r"(a[0]), "r"(a[1]), "r"(a[2]), "r"(a[3]), "r"(b[0]), "r"(b[1]));
}

// ---------------- HMMA GEMM: D[M,N] = alpha * A[M,K] @ B[N,K]^T ---------------
// A, B bf16, K-contiguous (ldA=ldB=K), D row-major ld=N. Tiles 128x128x64.
// OM: 0 = bf16 out + col bias[n]; 1 = bf16 out + row bias[m];
//     2 = bf16 out * alpha;       4 = fp32 out + row bias[m] + residual.
#define BM 128
#define BN 128
#define BK 64
#define ROWB 144                    // padded row pitch in bytes (64 halves + 8 pad)
#define MAT_BYTES (128 * ROWB)      // 18432 per matrix per stage
#define STAGE_BYTES (2 * MAT_BYTES) // 36864
#define STAGES 4
#define GEMM_SMEM (STAGES * STAGE_BYTES)

template<int OM>
__global__ __launch_bounds__(256, 1)
void hm_gemm(const bf16* __restrict__ A, const bf16* __restrict__ B, void* __restrict__ Cv,
             const float* __restrict__ bias, const float* __restrict__ resid,
             int M, int N, int K,
             long long sA, long long sB, long long sC, long long sR, float alpha)
{
    extern __shared__ __align__(16) char smem[];
    int t = threadIdx.x, w = t >> 5, lane = t & 31;
    int wm = w >> 2, wn = w & 3;                  // 2 x 4 warps -> warp tile 64 x 32
    int bz = blockIdx.z;
    const bf16* Ab = A + sA * bz;
    const bf16* Bb = B + sB * bz;
    int bm = blockIdx.y * BM;
    int bn = blockIdx.x * BN;
    uint32_t sbase = smem_u32(smem);

    // per-stage tile load: 128 rows x 8 chunks(16B) per matrix, 4 cp/thread/matrix
    auto load_chunk = [&](int kc, int s) {
        uint32_t sa = sbase + s * STAGE_BYTES;
        uint32_t sb = sa + MAT_BYTES;
        int k0 = kc * BK;
#pragma unroll
        for (int u = 0; u < 4; u++) {
            int idx = t + u * 256;
            int r = idx >> 3, c = idx & 7;
            cp_async16(sa + r * ROWB + c * 16, Ab + (size_t)(bm + r) * K + k0 + c * 8);
        }
#pragma unroll
        for (int u = 0; u < 4; u++) {
            int idx = t + u * 256;
            int r = idx >> 3, c = idx & 7;
            cp_async16(sb + r * ROWB + c * 16, Bb + (size_t)(bn + r) * K + k0 + c * 8);
        }
        CP_COMMIT();
    };

    // ldmatrix lane address offsets (bytes, relative to matrix base in stage)
    int lr = lane & 7, sub = lane >> 3;
    uint32_t offA = (uint32_t)((wm * 64 + (sub & 1) * 8 + lr) * ROWB + ((sub >> 1) * 8) * 2);
    uint32_t offB = (uint32_t)((wn * 32 + (sub >> 1) * 8 + lr) * ROWB + ((sub & 1) * 8) * 2);

    float acc[4][4][4];
#pragma unroll
    for (int i = 0; i < 4; i++)
#pragma unroll
        for (int j = 0; j < 4; j++)
#pragma unroll
            for (int q = 0; q < 4; q++) acc[i][j][q] = 0.f;

    uint32_t frA[2][4][4];    // [buf][m-tile][4 regs]
    uint32_t frB[2][2][4];    // [buf][n16 grp][4 regs] -> n8 op jj: grp jj>>1, regs (jj&1)*2..+1

    auto lds_frags = [&](uint32_t sb, int ks, int buf) {
        uint32_t ka = sb + offA + ks * 32;
#pragma unroll
        for (int i = 0; i < 4; i++) ldm4(frA[buf][i], ka + i * 16 * ROWB);
        uint32_t kb = sb + MAT_BYTES + offB + ks * 32;
#pragma unroll
        for (int j = 0; j < 2; j++) ldm4(frB[buf][j], kb + j * 16 * ROWB);
    };

    int nK = K / BK;
    load_chunk(0, 0); load_chunk(1, 1); load_chunk(2, 2);

    for (int kc = 0; kc < nK; kc++) {
        int s = kc & (STAGES - 1);
        CP_WAIT2();
        __syncthreads();
        if (kc + 3 < nK) load_chunk(kc + 3, (kc + 3) & (STAGES - 1));
        else CP_COMMIT();

        uint32_t sb = sbase + s * STAGE_BYTES;
        lds_frags(sb, 0, 0);
#pragma unroll
        for (int ks = 0; ks < 4; ks++) {
            if (ks < 3) lds_frags(sb, ks + 1, (ks + 1) & 1);
            int bu = ks & 1;
#pragma unroll
            for (int i = 0; i < 4; i++)
#pragma unroll
                for (int jj = 0; jj < 4; jj++)
                    mma16816(acc[i][jj], frA[bu][i], &frB[bu][jj >> 1][(jj & 1) * 2]);
        }
    }

    // ---------------- epilogue: direct stores from accumulators ---------------
#pragma unroll
    for (int i = 0; i < 4; i++) {
        int r0 = bm + wm * 64 + i * 16 + (lane >> 2);
#pragma unroll
        for (int jj = 0; jj < 4; jj++) {
            int col = bn + wn * 32 + jj * 8 + (lane & 3) * 2;
            float v0 = acc[i][jj][0], v1 = acc[i][jj][1];
            float v2 = acc[i][jj][2], v3 = acc[i][jj][3];
            if (OM == 2) { v0 *= alpha; v1 *= alpha; v2 *= alpha; v3 *= alpha; }
            if (OM == 0) {
                float b0 = bias[col], b1 = bias[col + 1];
                v0 += b0; v1 += b1; v2 += b0; v3 += b1;
            }
            if (OM == 1 || OM == 4) {
                float ba = bias[r0], bb = bias[r0 + 8];
                v0 += ba; v1 += ba; v2 += bb; v3 += bb;
            }
            size_t o0 = (size_t)r0 * N + col;
            size_t o1 = (size_t)(r0 + 8) * N + col;
            if (OM == 4) {
                float* C = (float*)Cv + sC * bz;
                const float* R = resid + sR * bz;
                float2 ra = *(const float2*)&R[o0];
                float2 rb = *(const float2*)&R[o1];
                *(float2*)&C[o0] = make_float2(v0 + ra.x, v1 + ra.y);
                *(float2*)&C[o1] = make_float2(v2 + rb.x, v3 + rb.y);
            } else {
                bf16* C = (bf16*)Cv + sC * bz;
                __nv_bfloat162 p0 = __floats2bfloat162_rn(v0, v1);
                __nv_bfloat162 p1 = __floats2bfloat162_rn(v2, v3);
                *(__nv_bfloat162*)&C[o0] = p0;
                *(__nv_bfloat162*)&C[o1] = p1;
            }
        }
    }
}

// ---------------- weight fp32 -> bf16 ----------------------------------------
__global__ void cvt_w_kernel(const float* __restrict__ qw, const float* __restrict__ kw,
                             const float* __restrict__ vw, const float* __restrict__ pw) {
    int i = blockIdx.x * 256 + threadIdx.x;
    if (i < ND * NC) {
        g_wq[i] = __float2bfloat16(qw[i]);
        g_wk[i] = __float2bfloat16(kw[i]);
        g_wv[i] = __float2bfloat16(vw[i]);
        g_wp[i] = __float2bfloat16(pw[i]);
    }
}

// ---------------- GN phase 1: per-(b,g) stats ---------------------------------
__global__ __launch_bounds__(256) void gn_stats_kernel(const float* __restrict__ x) {
    int bg = blockIdx.x;
    int b = bg >> 5, g = bg & 31;
    const float4* xp = (const float4*)(x + ((size_t)(b * NC + g * 16)) * NN_);
    int t = threadIdx.x;
    float s = 0.f, ss = 0.f;
    for (int i = t; i < 16384; i += 256) {
        float4 v = xp[i];
        s  += v.x + v.y + v.z + v.w;
        ss += v.x * v.x + v.y * v.y + v.z * v.z + v.w * v.w;
    }
    __shared__ float rs[256], rq[256];
    rs[t] = s; rq[t] = ss;
    __syncthreads();
    for (int st = 128; st > 0; st >>= 1) {
        if (t < st) { rs[t] += rs[t + st]; rq[t] += rq[t + st]; }
        __syncthreads();
    }
    if (t == 0) {
        float mean = rs[0] * (1.f / 65536.f);
        float var  = rq[0] * (1.f / 65536.f) - mean * mean;
        g_stats[bg] = make_float2(mean, rsqrtf(var + 1e-5f));
    }
}

// ---------------- GN phase 2: normalize + transpose -> hT [b][n][c] -----------
__global__ __launch_bounds__(256) void gn_apply_kernel(
    const float* __restrict__ x, const float* __restrict__ gamma,
    const float* __restrict__ beta)
{
    __shared__ __align__(16) bf16 ts[128][72];
    int n0 = blockIdx.x * 128, c0 = blockIdx.y * 64, b = blockIdx.z;
    int t = threadIdx.x;
#pragma unroll
    for (int u = 0; u < 8; u++) {
        int idx = t + u * 256;               // 2048 = 64c x 32 (n in float4)
        int c = idx >> 5, nv = idx & 31;
        float2 st = g_stats[b * 32 + ((c0 + c) >> 4)];
        float sc = gamma[c0 + c] * st.y;
        float sh = beta[c0 + c] - st.x * sc;
        float4 v = *(const float4*)(x + ((size_t)(b * NC + c0 + c)) * NN_ + n0 + nv * 4);
        ts[nv * 4 + 0][c] = __float2bfloat16(v.x * sc + sh);
        ts[nv * 4 + 1][c] = __float2bfloat16(v.y * sc + sh);
        ts[nv * 4 + 2][c] = __float2bfloat16(v.z * sc + sh);
        ts[nv * 4 + 3][c] = __float2bfloat16(v.w * sc + sh);
    }
    __syncthreads();
#pragma unroll
    for (int u = 0; u < 4; u++) {
        int idx = t + u * 256;               // 1024 = 128n x 8 (c in uint4)
        int n = idx >> 3, cq = idx & 7;
        uint4 val = *(uint4*)&ts[n][cq * 8];
        *(uint4*)&g_hT[((size_t)(b * NN_ + n0 + n)) * NC + c0 + cq * 8] = val;
    }
}

// ---------------- softmax in place over bf16 S rows ---------------------------
__global__ __launch_bounds__(256) void softmax_kernel() {
    size_t row = blockIdx.x;
    uint4* sp = (uint4*)(g_S + row * NN_);   // 512 uint4 per row
    int t = threadIdx.x;
    uint4 v0 = sp[t], v1 = sp[t + 256];
    float e[16];
    {
        const uint32_t* w0 = (const uint32_t*)&v0;
        const uint32_t* w1 = (const uint32_t*)&v1;
#pragma unroll
        for (int i = 0; i < 4; i++) {
            float2 a = __bfloat1622float2(*(__nv_bfloat162*)&w0[i]);
            e[2 * i] = a.x; e[2 * i + 1] = a.y;
            float2 c = __bfloat1622float2(*(__nv_bfloat162*)&w1[i]);
            e[8 + 2 * i] = c.x; e[8 + 2 * i + 1] = c.y;
        }
    }
    float mx = -1e30f;
#pragma unroll
    for (int i = 0; i < 16; i++) mx = fmaxf(mx, e[i]);
    __shared__ float red[256];
    red[t] = mx; __syncthreads();
    for (int st = 128; st > 0; st >>= 1) {
        if (t < st) red[t] = fmaxf(red[t], red[t + st]);
        __syncthreads();
    }
    float m = red[0];
    __syncthreads();
    float sum = 0.f;
#pragma unroll
    for (int i = 0; i < 16; i++) { e[i] = __expf(e[i] - m); sum += e[i]; }
    red[t] = sum; __syncthreads();
    for (int st = 128; st > 0; st >>= 1) {
        if (t < st) red[t] += red[t + st];
        __syncthreads();
    }
    float inv = 1.f / red[0];
    uint4 o0, o1;
    uint32_t* w0 = (uint32_t*)&o0;
    uint32_t* w1 = (uint32_t*)&o1;
#pragma unroll
    for (int i = 0; i < 4; i++) {
        __nv_bfloat162 a = __floats2bfloat162_rn(e[2 * i] * inv, e[2 * i + 1] * inv);
        w0[i] = *(uint32_t*)&a;
        __nv_bfloat162 c = __floats2bfloat162_rn(e[8 + 2 * i] * inv, e[9 + 2 * i] * inv);
        w1[i] = *(uint32_t*)&c;
    }
    sp[t] = o0; sp[t + 256] = o1;
}

// ---------------- launch ------------------------------------------------------
static void* sym_addr(const void* s) { void* p = nullptr; cudaGetSymbolAddress(&p, s); return p; }

extern "C" void kernel_launch(void* const* d_in, const int* in_sizes, int n_in,
                              void* d_out, int out_size) {
    const float* x   = (const float*)d_in[0];
    const float* gnw = (const float*)d_in[1];
    const float* gnb = (const float*)d_in[2];
    const float* qw  = (const float*)d_in[3];
    const float* qb  = (const float*)d_in[4];
    const float* kw  = (const float*)d_in[5];
    const float* kb  = (const float*)d_in[6];
    const float* vw  = (const float*)d_in[7];
    const float* vb  = (const float*)d_in[8];
    const float* pw  = (const float*)d_in[9];
    const float* pb  = (const float*)d_in[10];

    bf16* p_hT  = (bf16*)sym_addr(g_hT);
    bf16* p_qT  = (bf16*)sym_addr(g_qT);
    bf16* p_kT  = (bf16*)sym_addr(g_kT);
    bf16* p_v   = (bf16*)sym_addr(g_v);
    bf16* p_S   = (bf16*)sym_addr(g_S);
    bf16* p_hfT = (bf16*)sym_addr(g_hfT);
    bf16* p_wq  = (bf16*)sym_addr(g_wq);
    bf16* p_wk  = (bf16*)sym_addr(g_wk);
    bf16* p_wv  = (bf16*)sym_addr(g_wv);
    bf16* p_wp  = (bf16*)sym_addr(g_wp);

    static bool attr_done = false;
    if (!attr_done) {
        cudaFuncSetAttribute(hm_gemm<0>, cudaFuncAttributeMaxDynamicSharedMemorySize, GEMM_SMEM);
        cudaFuncSetAttribute(hm_gemm<1>, cudaFuncAttributeMaxDynamicSharedMemorySize, GEMM_SMEM);
        cudaFuncSetAttribute(hm_gemm<2>, cudaFuncAttributeMaxDynamicSharedMemorySize, GEMM_SMEM);
        cudaFuncSetAttribute(hm_gemm<4>, cudaFuncAttributeMaxDynamicSharedMemorySize, GEMM_SMEM);
        attr_done = true;
    }

    const long long sT  = (long long)NN_ * ND;   // batch stride for hT/qT/kT/v/hfT
    const long long sSS = (long long)NN_ * NN_;
    const float scale = 0.044194173824159216f;   // 512^-0.5

    cvt_w_kernel<<<1024, 256>>>(qw, kw, vw, pw);
    gn_stats_kernel<<<NB * 32, 256>>>(x);
    gn_apply_kernel<<<dim3(32, 8, NB), 256>>>(x, gnw, gnb);

    // qT[n,d] = hT @ Wq^T + qb[d]   (col bias)
    hm_gemm<0><<<dim3(4, 32, NB), 256, GEMM_SMEM>>>(p_hT, p_wq, p_qT, qb, nullptr,
        NN_, ND, NC, sT, 0, sT, 0, 1.f);
    // kT[m,d] = hT @ Wk^T + kb[d]
    hm_gemm<0><<<dim3(4, 32, NB), 256, GEMM_SMEM>>>(p_hT, p_wk, p_kT, kb, nullptr,
        NN_, ND, NC, sT, 0, sT, 0, 1.f);
    // v[d,m] = Wv @ hT^T + vb[d]    (row bias)
    hm_gemm<1><<<dim3(32, 4, NB), 256, GEMM_SMEM>>>(p_wv, p_hT, p_v, vb, nullptr,
        ND, NN_, NC, 0, sT, sT, 0, 1.f);
    // S[n,m] = scale * qT @ kT^T    (bf16)
    hm_gemm<2><<<dim3(32, 32, NB), 256, GEMM_SMEM>>>(p_qT, p_kT, p_S, nullptr, nullptr,
        NN_, NN_, ND, sT, sT, sSS, 0, scale);
    // P = softmax(S) in place
    softmax_kernel<<<NB * NN_, 256>>>();
    // hfT[n,d] = P @ v^T
    hm_gemm<2><<<dim3(4, 32, NB), 256, GEMM_SMEM>>>(p_S, p_v, p_hfT, nullptr, nullptr,
        NN_, ND, NN_, sSS, sT, sT, 0, 1.f);
    // out[c,n] = Wp @ hfT^T + pb[c] + x   (fp32 + residual)
    hm_gemm<4><<<dim3(32, 4, NB), 256, GEMM_SMEM>>>(p_wp, p_hfT, d_out, pb, x,
        NC, NN_, ND, 0, sT, (long long)NC * NN_, (long long)NC * NN_, 1.f);
}

// round 9
// speedup vs baseline: 2.7537x; 1.0859x over previous
#include <cuda_runtime.h>
#include <cuda_bf16.h>
#include <cstdint>

typedef __nv_bfloat16 bf16;

// Problem dims: B=8, C=512, H=W=64 -> N=4096, att=512
#define NB 8
#define NC 512
#define NN_ 4096
#define ND 512

// ---------------- scratch (static device globals) ---------------------------
__device__ __align__(1024) bf16  g_hT [(size_t)NB * NN_ * NC];  // [b][n][c]
__device__ __align__(1024) bf16  g_qT [(size_t)NB * NN_ * ND];  // [b][n][d]
__device__ __align__(1024) bf16  g_kT [(size_t)NB * NN_ * ND];  // [b][m][d]
__device__ __align__(1024) bf16  g_v  [(size_t)NB * ND * NN_];  // [b][d][m]
__device__ __align__(1024) bf16  g_S  [(size_t)NB * NN_ * NN_]; // [b][n][m] (256MB)
__device__ __align__(1024) bf16  g_hfT[(size_t)NB * NN_ * ND];  // [b][n][d]
__device__ __align__(1024) bf16  g_wq [ND * NC];
__device__ __align__(1024) bf16  g_wk [ND * NC];
__device__ __align__(1024) bf16  g_wv [ND * NC];
__device__ __align__(1024) bf16  g_wp [NC * ND];
__device__ float2 g_stats[NB * 32];                             // per (b,g): mean, inv

// ---------------- helpers -----------------------------------------------------
__device__ __forceinline__ uint32_t smem_u32(const void* p) {
    uint32_t a;
    asm("{ .reg .u64 t; cvta.to.shared.u64 t, %1; cvt.u32.u64 %0, t; }" : "=r"(a) : "l"(p));
    return a;
}
__device__ __forceinline__ void cp_async16(uint32_t s, const void* g) {
    asm volatile("cp.async.cg.shared.global [%0], [%1], 16;" :: "r"(s), "l"(g));
}
#define CP_COMMIT()  asm volatile("cp.async.commit_group;" ::: "memory")
#define CP_WAIT1()   asm volatile("cp.async.wait_group 1;" ::: "memory")

__device__ __forceinline__ void ldm4(uint32_t* r, uint32_t addr) {
    asm volatile("ldmatrix.sync.aligned.m8n8.x4.shared.b16 {%0,%1,%2,%3}, [%4];"
        : "=r"(r[0]), "=r"(r[1]), "=r"(r[2]), "=r"(r[3]) : "r"(addr));
}
__device__ __forceinline__ void mma16816(float* d, const uint32_t* a, const uint32_t* b) {
    asm volatile(
        "mma.sync.aligned.m16n8k16.row.col.f32.bf16.bf16.f32 "
        "{%0,%1,%2,%3}, {%4,%5,%6,%7}, {%8,%9}, {%0,%1,%2,%3};"
        : "+f"(d[0]), "+f"(d[1]), "+f"(d[2]), "+f"(d[3])
        : "r"(a[0]), "r"(a[1]), "r"(a[2]), "r"(a[3]), "r"(b[0]), "r"(b[1]));
}

// ---------------- HMMA GEMM: D[M,N] = alpha * A[M,K] @ B[N,K]^T ---------------
// A, B bf16, K-contiguous (ldA=ldB=K), D row-major ld=N.
// CTA tile 128x256x64, 512 threads, 16 warps (2x8), warp tile 64x32.
// OM: 0 = bf16 out + col bias[n]; 1 = bf16 out + row bias[m];
//     2 = bf16 out * alpha;       4 = fp32 out + row bias[m] + residual.
#define BM 128
#define BN 256
#define BK 64
#define NT 512                      // threads per CTA
#define ROWB 144                    // padded row pitch in bytes (64 halves + 8 pad)
#define A_BYTES (BM * ROWB)         // 18432
#define B_BYTES (BN * ROWB)         // 36864
#define STAGE_BYTES (A_BYTES + B_BYTES) // 55296
#define STAGES 3
#define GEMM_SMEM (STAGES * STAGE_BYTES)

template<int OM>
__global__ __launch_bounds__(NT, 1)
void hm_gemm(const bf16* __restrict__ A, const bf16* __restrict__ B, void* __restrict__ Cv,
             const float* __restrict__ bias, const float* __restrict__ resid,
             int M, int N, int K,
             long long sA, long long sB, long long sC, long long sR, float alpha)
{
    extern __shared__ __align__(16) char smem[];
    int t = threadIdx.x, w = t >> 5, lane = t & 31;
    int wm = w >> 3, wn = w & 7;                  // 2 x 8 warps -> warp tile 64 x 32
    int bz = blockIdx.z;
    const bf16* Ab = A + sA * bz;
    const bf16* Bb = B + sB * bz;
    int bm = blockIdx.y * BM;
    int bn = blockIdx.x * BN;
    uint32_t sbase = smem_u32(smem);

    // per-stage tile load: A 128 rows x 8 chunks(16B) = 2/thr, B 256 rows = 4/thr
    auto load_chunk = [&](int kc, int s) {
        uint32_t sa = sbase + s * STAGE_BYTES;
        uint32_t sb = sa + A_BYTES;
        int k0 = kc * BK;
#pragma unroll
        for (int u = 0; u < 2; u++) {
            int idx = t + u * NT;
            int r = idx >> 3, c = idx & 7;
            cp_async16(sa + r * ROWB + c * 16, Ab + (size_t)(bm + r) * K + k0 + c * 8);
        }
#pragma unroll
        for (int u = 0; u < 4; u++) {
            int idx = t + u * NT;
            int r = idx >> 3, c = idx & 7;
            cp_async16(sb + r * ROWB + c * 16, Bb + (size_t)(bn + r) * K + k0 + c * 8);
        }
        CP_COMMIT();
    };

    // ldmatrix lane address offsets (bytes, relative to matrix base in stage)
    int lr = lane & 7, sub = lane >> 3;
    uint32_t offA = (uint32_t)((wm * 64 + (sub & 1) * 8 + lr) * ROWB + ((sub >> 1) * 8) * 2);
    uint32_t offB = (uint32_t)((wn * 32 + (sub >> 1) * 8 + lr) * ROWB + ((sub & 1) * 8) * 2);

    float acc[4][4][4];
#pragma unroll
    for (int i = 0; i < 4; i++)
#pragma unroll
        for (int j = 0; j < 4; j++)
#pragma unroll
            for (int q = 0; q < 4; q++) acc[i][j][q] = 0.f;

    uint32_t frA[4][4];   // [m-tile][4 regs]
    uint32_t frB[2][4];   // [n16 grp][4 regs]; n8 op jj: grp jj>>1, regs (jj&1)*2..+1

    int nK = K / BK;
    load_chunk(0, 0); load_chunk(1, 1);

    int s = 0, sp = 2;
    for (int kc = 0; kc < nK; kc++) {
        CP_WAIT1();
        __syncthreads();
        if (kc + 2 < nK) load_chunk(kc + 2, sp);
        else CP_COMMIT();

        uint32_t sb = sbase + s * STAGE_BYTES;
#pragma unroll
        for (int ks = 0; ks < 4; ks++) {
            uint32_t ka = sb + offA + ks * 32;
#pragma unroll
            for (int i = 0; i < 4; i++) ldm4(frA[i], ka + i * 16 * ROWB);
            uint32_t kb = sb + A_BYTES + offB + ks * 32;
#pragma unroll
            for (int j = 0; j < 2; j++) ldm4(frB[j], kb + j * 16 * ROWB);
#pragma unroll
            for (int i = 0; i < 4; i++)
#pragma unroll
                for (int jj = 0; jj < 4; jj++)
                    mma16816(acc[i][jj], frA[i], &frB[jj >> 1][(jj & 1) * 2]);
        }
        s  = (s  == STAGES - 1) ? 0 : s + 1;
        sp = (sp == STAGES - 1) ? 0 : sp + 1;
    }

    // ---------------- epilogue: direct stores from accumulators ---------------
#pragma unroll
    for (int i = 0; i < 4; i++) {
        int r0 = bm + wm * 64 + i * 16 + (lane >> 2);
#pragma unroll
        for (int jj = 0; jj < 4; jj++) {
            int col = bn + wn * 32 + jj * 8 + (lane & 3) * 2;
            float v0 = acc[i][jj][0], v1 = acc[i][jj][1];
            float v2 = acc[i][jj][2], v3 = acc[i][jj][3];
            if (OM == 2) { v0 *= alpha; v1 *= alpha; v2 *= alpha; v3 *= alpha; }
            if (OM == 0) {
                float b0 = bias[col], b1 = bias[col + 1];
                v0 += b0; v1 += b1; v2 += b0; v3 += b1;
            }
            if (OM == 1 || OM == 4) {
                float ba = bias[r0], bb = bias[r0 + 8];
                v0 += ba; v1 += ba; v2 += bb; v3 += bb;
            }
            size_t o0 = (size_t)r0 * N + col;
            size_t o1 = (size_t)(r0 + 8) * N + col;
            if (OM == 4) {
                float* C = (float*)Cv + sC * bz;
                const float* R = resid + sR * bz;
                float2 ra = *(const float2*)&R[o0];
                float2 rb = *(const float2*)&R[o1];
                *(float2*)&C[o0] = make_float2(v0 + ra.x, v1 + ra.y);
                *(float2*)&C[o1] = make_float2(v2 + rb.x, v3 + rb.y);
            } else {
                bf16* C = (bf16*)Cv + sC * bz;
                __nv_bfloat162 p0 = __floats2bfloat162_rn(v0, v1);
                __nv_bfloat162 p1 = __floats2bfloat162_rn(v2, v3);
                *(__nv_bfloat162*)&C[o0] = p0;
                *(__nv_bfloat162*)&C[o1] = p1;
            }
        }
    }
}

// ---------------- weight fp32 -> bf16 ----------------------------------------
__global__ void cvt_w_kernel(const float* __restrict__ qw, const float* __restrict__ kw,
                             const float* __restrict__ vw, const float* __restrict__ pw) {
    int i = blockIdx.x * 256 + threadIdx.x;
    if (i < ND * NC) {
        g_wq[i] = __float2bfloat16(qw[i]);
        g_wk[i] = __float2bfloat16(kw[i]);
        g_wv[i] = __float2bfloat16(vw[i]);
        g_wp[i] = __float2bfloat16(pw[i]);
    }
}

// ---------------- GN phase 1: per-(b,g) stats ---------------------------------
__global__ __launch_bounds__(256) void gn_stats_kernel(const float* __restrict__ x) {
    int bg = blockIdx.x;
    int b = bg >> 5, g = bg & 31;
    const float4* xp = (const float4*)(x + ((size_t)(b * NC + g * 16)) * NN_);
    int t = threadIdx.x;
    float s = 0.f, ss = 0.f;
    for (int i = t; i < 16384; i += 256) {
        float4 v = xp[i];
        s  += v.x + v.y + v.z + v.w;
        ss += v.x * v.x + v.y * v.y + v.z * v.z + v.w * v.w;
    }
    __shared__ float rs[256], rq[256];
    rs[t] = s; rq[t] = ss;
    __syncthreads();
    for (int st = 128; st > 0; st >>= 1) {
        if (t < st) { rs[t] += rs[t + st]; rq[t] += rq[t + st]; }
        __syncthreads();
    }
    if (t == 0) {
        float mean = rs[0] * (1.f / 65536.f);
        float var  = rq[0] * (1.f / 65536.f) - mean * mean;
        g_stats[bg] = make_float2(mean, rsqrtf(var + 1e-5f));
    }
}

// ---------------- GN phase 2: normalize + transpose -> hT [b][n][c] -----------
__global__ __launch_bounds__(256) void gn_apply_kernel(
    const float* __restrict__ x, const float* __restrict__ gamma,
    const float* __restrict__ beta)
{
    __shared__ __align__(16) bf16 ts[128][72];
    int n0 = blockIdx.x * 128, c0 = blockIdx.y * 64, b = blockIdx.z;
    int t = threadIdx.x;
#pragma unroll
    for (int u = 0; u < 8; u++) {
        int idx = t + u * 256;               // 2048 = 64c x 32 (n in float4)
        int c = idx >> 5, nv = idx & 31;
        float2 st = g_stats[b * 32 + ((c0 + c) >> 4)];
        float sc = gamma[c0 + c] * st.y;
        float sh = beta[c0 + c] - st.x * sc;
        float4 v = *(const float4*)(x + ((size_t)(b * NC + c0 + c)) * NN_ + n0 + nv * 4);
        ts[nv * 4 + 0][c] = __float2bfloat16(v.x * sc + sh);
        ts[nv * 4 + 1][c] = __float2bfloat16(v.y * sc + sh);
        ts[nv * 4 + 2][c] = __float2bfloat16(v.z * sc + sh);
        ts[nv * 4 + 3][c] = __float2bfloat16(v.w * sc + sh);
    }
    __syncthreads();
#pragma unroll
    for (int u = 0; u < 4; u++) {
        int idx = t + u * 256;               // 1024 = 128n x 8 (c in uint4)
        int n = idx >> 3, cq = idx & 7;
        uint4 val = *(uint4*)&ts[n][cq * 8];
        *(uint4*)&g_hT[((size_t)(b * NN_ + n0 + n)) * NC + c0 + cq * 8] = val;
    }
}

// ---------------- softmax in place over bf16 S rows ---------------------------
__global__ __launch_bounds__(256) void softmax_kernel() {
    size_t row = blockIdx.x;
    uint4* sp = (uint4*)(g_S + row * NN_);   // 512 uint4 per row
    int t = threadIdx.x;
    uint4 v0 = sp[t], v1 = sp[t + 256];
    float e[16];
    {
        const uint32_t* w0 = (const uint32_t*)&v0;
        const uint32_t* w1 = (const uint32_t*)&v1;
#pragma unroll
        for (int i = 0; i < 4; i++) {
            float2 a = __bfloat1622float2(*(__nv_bfloat162*)&w0[i]);
            e[2 * i] = a.x; e[2 * i + 1] = a.y;
            float2 c = __bfloat1622float2(*(__nv_bfloat162*)&w1[i]);
            e[8 + 2 * i] = c.x; e[8 + 2 * i + 1] = c.y;
        }
    }
    float mx = -1e30f;
#pragma unroll
    for (int i = 0; i < 16; i++) mx = fmaxf(mx, e[i]);
    __shared__ float red[256];
    red[t] = mx; __syncthreads();
    for (int st = 128; st > 0; st >>= 1) {
        if (t < st) red[t] = fmaxf(red[t], red[t + st]);
        __syncthreads();
    }
    float m = red[0];
    __syncthreads();
    float sum = 0.f;
#pragma unroll
    for (int i = 0; i < 16; i++) { e[i] = __expf(e[i] - m); sum += e[i]; }
    red[t] = sum; __syncthreads();
    for (int st = 128; st > 0; st >>= 1) {
        if (t < st) red[t] += red[t + st];
        __syncthreads();
    }
    float inv = 1.f / red[0];
    uint4 o0, o1;
    uint32_t* w0 = (uint32_t*)&o0;
    uint32_t* w1 = (uint32_t*)&o1;
#pragma unroll
    for (int i = 0; i < 4; i++) {
        __nv_bfloat162 a = __floats2bfloat162_rn(e[2 * i] * inv, e[2 * i + 1] * inv);
        w0[i] = *(uint32_t*)&a;
        __nv_bfloat162 c = __floats2bfloat162_rn(e[8 + 2 * i] * inv, e[9 + 2 * i] * inv);
        w1[i] = *(uint32_t*)&c;
    }
    sp[t] = o0; sp[t + 256] = o1;
}

// ---------------- launch ------------------------------------------------------
static void* sym_addr(const void* s) { void* p = nullptr; cudaGetSymbolAddress(&p, s); return p; }

extern "C" void kernel_launch(void* const* d_in, const int* in_sizes, int n_in,
                              void* d_out, int out_size) {
    const float* x   = (const float*)d_in[0];
    const float* gnw = (const float*)d_in[1];
    const float* gnb = (const float*)d_in[2];
    const float* qw  = (const float*)d_in[3];
    const float* qb  = (const float*)d_in[4];
    const float* kw  = (const float*)d_in[5];
    const float* kb  = (const float*)d_in[6];
    const float* vw  = (const float*)d_in[7];
    const float* vb  = (const float*)d_in[8];
    const float* pw  = (const float*)d_in[9];
    const float* pb  = (const float*)d_in[10];

    bf16* p_hT  = (bf16*)sym_addr(g_hT);
    bf16* p_qT  = (bf16*)sym_addr(g_qT);
    bf16* p_kT  = (bf16*)sym_addr(g_kT);
    bf16* p_v   = (bf16*)sym_addr(g_v);
    bf16* p_S   = (bf16*)sym_addr(g_S);
    bf16* p_hfT = (bf16*)sym_addr(g_hfT);
    bf16* p_wq  = (bf16*)sym_addr(g_wq);
    bf16* p_wk  = (bf16*)sym_addr(g_wk);
    bf16* p_wv  = (bf16*)sym_addr(g_wv);
    bf16* p_wp  = (bf16*)sym_addr(g_wp);

    static bool attr_done = false;
    if (!attr_done) {
        cudaFuncSetAttribute(hm_gemm<0>, cudaFuncAttributeMaxDynamicSharedMemorySize, GEMM_SMEM);
        cudaFuncSetAttribute(hm_gemm<1>, cudaFuncAttributeMaxDynamicSharedMemorySize, GEMM_SMEM);
        cudaFuncSetAttribute(hm_gemm<2>, cudaFuncAttributeMaxDynamicSharedMemorySize, GEMM_SMEM);
        cudaFuncSetAttribute(hm_gemm<4>, cudaFuncAttributeMaxDynamicSharedMemorySize, GEMM_SMEM);
        attr_done = true;
    }

    const long long sT  = (long long)NN_ * ND;   // batch stride for hT/qT/kT/v/hfT
    const long long sSS = (long long)NN_ * NN_;
    const float scale = 0.044194173824159216f;   // 512^-0.5

    cvt_w_kernel<<<1024, 256>>>(qw, kw, vw, pw);
    gn_stats_kernel<<<NB * 32, 256>>>(x);
    gn_apply_kernel<<<dim3(32, 8, NB), 256>>>(x, gnw, gnb);

    // qT[n,d] = hT @ Wq^T + qb[d]   (col bias)
    hm_gemm<0><<<dim3(2, 32, NB), NT, GEMM_SMEM>>>(p_hT, p_wq, p_qT, qb, nullptr,
        NN_, ND, NC, sT, 0, sT, 0, 1.f);
    // kT[m,d] = hT @ Wk^T + kb[d]
    hm_gemm<0><<<dim3(2, 32, NB), NT, GEMM_SMEM>>>(p_hT, p_wk, p_kT, kb, nullptr,
        NN_, ND, NC, sT, 0, sT, 0, 1.f);
    // v[d,m] = Wv @ hT^T + vb[d]    (row bias)
    hm_gemm<1><<<dim3(16, 4, NB), NT, GEMM_SMEM>>>(p_wv, p_hT, p_v, vb, nullptr,
        ND, NN_, NC, 0, sT, sT, 0, 1.f);
    // S[n,m] = scale * qT @ kT^T    (bf16)
    hm_gemm<2><<<dim3(16, 32, NB), NT, GEMM_SMEM>>>(p_qT, p_kT, p_S, nullptr, nullptr,
        NN_, NN_, ND, sT, sT, sSS, 0, scale);
    // P = softmax(S) in place
    softmax_kernel<<<NB * NN_, 256>>>();
    // hfT[n,d] = P @ v^T
    hm_gemm<2><<<dim3(2, 32, NB), NT, GEMM_SMEM>>>(p_S, p_v, p_hfT, nullptr, nullptr,
        NN_, ND, NN_, sSS, sT, sT, 0, 1.f);
    // out[c,n] = Wp @ hfT^T + pb[c] + x   (fp32 + residual)
    hm_gemm<4><<<dim3(16, 4, NB), NT, GEMM_SMEM>>>(p_wp, p_hfT, d_out, pb, x,
        NC, NN_, ND, 0, sT, (long long)NC * NN_, (long long)NC * NN_, 1.f);
}